// round 5
// baseline (speedup 1.0000x reference)
#include <cuda_runtime.h>
#include <cuda_bf16.h>
#include <cstdint>

// Problem constants
#define NN 2048
#define NROWS 16384
#define ROWS_PER_BLOCK 4
#define THREADS 512          // 16 warps: 4 warps per row
#define CHUNK 16             // elements per lane
#define NCHUNK 128           // chunks per row
// padded layout: p(k) = k + (k>>5); row stride = 2048 + 64 = 2112 words
#define PADSTRIDE 2112
#define PTOP 2110            // p(2047)

__device__ float g_cs[NN];
__device__ float g_sn[NN];
__device__ float g_wA[NN];    // stage-2 dot-product weights (row-independent)
__device__ float g_Bc[NCHUNK]; // per-chunk carry multiplier  (row-independent)

// Single-block precompute: sincos + chunk weights
__global__ void rg_precompute_kernel(const float* __restrict__ angles) {
    __shared__ float sc[NN];
    __shared__ float ss[NN];
    const int tid = threadIdx.x;
    for (int k = tid; k < NN; k += blockDim.x) {
        float s, c;
        sincosf(angles[k], &s, &c);
        sc[k] = c; ss[k] = s;
        g_cs[k] = c; g_sn[k] = s;
    }
    __syncthreads();
    // wA[k] = cos_k * prod_{v=chunkstart..k-1}(-sin_v);  Bc = prod over chunk
    for (int C = tid; C < NCHUNK; C += blockDim.x) {
        float run = 1.0f;
        #pragma unroll
        for (int t = 0; t < CHUNK; t++) {
            int k = CHUNK * C + t;
            g_wA[k] = run * sc[k];
            run = run * (-ss[k]);
        }
        g_Bc[C] = run;
    }
}

// 4 warps per row, chunk-16 affine-scan Givens application.
__global__ __launch_bounds__(THREADS, 2)
void rg_givens_kernel(const float* __restrict__ x, float* __restrict__ y) {
    extern __shared__ float sm[];
    float* xs   = sm;                                   // [4][PADSTRIDE]
    float* c_s  = sm + ROWS_PER_BLOCK * PADSTRIDE;      // [PADSTRIDE]
    float* s_s  = c_s + PADSTRIDE;                      // [PADSTRIDE]
    float* wA_s = s_s + PADSTRIDE;                      // [PADSTRIDE]
    float* wmA  = wA_s + PADSTRIDE;                     // [4 rows][4 warps]
    float* wmB  = wmA + 16;                             // [4 rows][4 warps]

    const int tid  = threadIdx.x;
    const int lane = tid & 31;
    const int w    = tid >> 5;
    const int rib  = w >> 2;          // row in block
    const int h    = w & 3;           // quarter of row
    const int row  = blockIdx.x * ROWS_PER_BLOCK + rib;
    float* xr = xs + rib * PADSTRIDE;

    // ---- Stage 1: staging ----
    const float4* xrow = (const float4*)(x + (size_t)row * NN);
    #pragma unroll
    for (int i = 0; i < 4; i++) {
        int v4 = h * 128 + i * 32 + lane;
        float4 val = xrow[v4];
        int k = v4 * 4;
        int p = k + (k >> 5);
        xr[p + 0] = val.x;
        xr[p + 1] = val.y;
        xr[p + 2] = val.z;
        xr[p + 3] = val.w;
    }
    // tables block-wide into padded smem (conflict-free scalar layout)
    #pragma unroll
    for (int k = tid; k < NN; k += THREADS) {
        int p = k + (k >> 5);
        c_s[p]  = g_cs[k];
        s_s[p]  = g_sn[k];
        wA_s[p] = g_wA[k];
    }
    __syncthreads();

    const float x0 = xr[0];
    // w0 = s_top*x_2047 + c_top*x_0 (replaces x~_0); computed by warp h==0
    float w0 = 0.0f;
    if (h == 0) {
        float xT = xr[PTOP];
        w0 = fmaf(s_s[PTOP], xT, c_s[PTOP] * x0);
    }

    const int C = h * 32 + lane;       // global chunk id 0..127
    const int pbase = 16 * C + (C >> 1);

    // ---- Chunk x into registers (conflict-free scalar LDS) ----
    float xv[CHUNK];
    #pragma unroll
    for (int t = 0; t < CHUNK; t++) xv[t] = xr[pbase + t];
    if (C == 0) xv[0] = w0;

    // ---- Stage 2: chunk affine map as a dot product (ILP-4) ----
    float A0 = 0.f, A1 = 0.f, A2 = 0.f, A3 = 0.f;
    #pragma unroll
    for (int t = 0; t < CHUNK; t += 4) {
        A0 = fmaf(wA_s[pbase + t + 0], xv[t + 0], A0);
        A1 = fmaf(wA_s[pbase + t + 1], xv[t + 1], A1);
        A2 = fmaf(wA_s[pbase + t + 2], xv[t + 2], A2);
        A3 = fmaf(wA_s[pbase + t + 3], xv[t + 3], A3);
    }
    float A  = (A0 + A1) + (A2 + A3);
    float Bm = g_Bc[C];                // coalesced LDG, L1-resident

    // ---- Warp suffix scan of affine maps ----
    float gA = A, gB = Bm;
    #pragma unroll
    for (int d = 1; d < 32; d <<= 1) {
        float A2s = __shfl_down_sync(0xffffffffu, gA, d);
        float B2s = __shfl_down_sync(0xffffffffu, gB, d);
        if (lane + d < 32) {
            gA = fmaf(gB, A2s, gA);
            gB = gB * B2s;
        }
    }
    float nA = __shfl_down_sync(0xffffffffu, gA, 1);
    float nB = __shfl_down_sync(0xffffffffu, gB, 1);

    // publish per-warp full maps
    if (lane == 0) {
        wmA[rib * 4 + h] = gA;
        wmB[rib * 4 + h] = gB;
    }
    __syncthreads();

    // entering carry for this warp = (W_{h+1} o ... o W_3)(x0)
    float cin = x0;
    #pragma unroll
    for (int j = 3; j >= 1; j--) {
        if (j > h) cin = fmaf(wmB[rib * 4 + j], cin, wmA[rib * 4 + j]);
    }
    float carry = (lane == 31) ? cin : fmaf(nB, cin, nA);

    // ---- Stage 3: replay with true carry; write y into xs ----
    const int pnext = 16 * (C + 1) + ((C + 1) >> 1);
    #pragma unroll
    for (int t = CHUNK - 1; t >= 0; t--) {
        float lc = c_s[pbase + t];
        float ls = s_s[pbase + t];
        float out = fmaf(lc, carry, ls * xv[t]);
        carry = fmaf(-ls, carry, lc * xv[t]);
        if (t == CHUNK - 1) {
            if (C != 127) xr[pnext] = out;     // y[16(C+1)]
        } else {
            xr[pbase + t + 1] = out;           // y[16C + t + 1]
        }
    }
    if (C == 0) xr[0] = carry;                 // y[0]
    __syncthreads();

    // ---- Store: padded smem -> coalesced float4 ----
    float4* yrow = (float4*)(y + (size_t)row * NN);
    #pragma unroll
    for (int i = 0; i < 4; i++) {
        int v4 = h * 128 + i * 32 + lane;
        int k = v4 * 4;
        int p = k + (k >> 5);
        float4 val;
        val.x = xr[p + 0];
        val.y = xr[p + 1];
        val.z = xr[p + 2];
        val.w = xr[p + 3];
        yrow[v4] = val;
    }
}

extern "C" void kernel_launch(void* const* d_in, const int* in_sizes, int n_in,
                              void* d_out, int out_size) {
    const float* x      = (const float*)d_in[0];   // [16384, 2048] fp32
    const float* angles = (const float*)d_in[1];   // [2048] fp32
    float* y = (float*)d_out;                      // [16384, 2048] fp32

    (void)in_sizes; (void)n_in; (void)out_size;

    rg_precompute_kernel<<<1, 256>>>(angles);

    const int smem_bytes = (ROWS_PER_BLOCK * PADSTRIDE + 3 * PADSTRIDE + 32) * sizeof(float);
    static bool attr_set = false;
    if (!attr_set) {
        cudaFuncSetAttribute(rg_givens_kernel,
                             cudaFuncAttributeMaxDynamicSharedMemorySize, smem_bytes);
        attr_set = true;
    }
    rg_givens_kernel<<<NROWS / ROWS_PER_BLOCK, THREADS, smem_bytes>>>(x, y);
}